// round 3
// baseline (speedup 1.0000x reference)
#include <cuda_runtime.h>

// Problem shape (fixed by the reference):
//   query [4,256,256], key [4,1024,256], Wq [256,256], Wk [256,256], v [256], v_bias [1]
//   out = softmax_s( sum_h v[h]*tanh(q[bt,h]+k[bs,h]) + vb )  -> [4,256,1024] fp32
#define BSZ 4
#define TGT 256
#define SRC 1024
#define HS  256

// Scratch for the projected q/k (allocation-free rule: __device__ globals).
__device__ __align__(16) float g_q[BSZ * TGT * HS];   // [1024, 256]
__device__ __align__(16) float g_k[BSZ * SRC * HS];   // [4096, 256]

// ---------------------------------------------------------------------------
// NT GEMM: C[m,n] = sum_k A[m,k] * B[n,k]   (A row-major [M,K], B row-major [N,K])
// Fixed N=K=256. which==0 -> C=g_q, which==1 -> C=g_k.
// BM=BN=64, BK=16, 256 threads, 4x4 per thread.
// ---------------------------------------------------------------------------
__global__ void __launch_bounds__(256) gemm_nt_kernel(const float* __restrict__ A,
                                                      const float* __restrict__ B,
                                                      int which) {
    const int K = HS, N = HS;
    float* __restrict__ C = which ? g_k : g_q;

    __shared__ float sA[16][64];
    __shared__ float sB[16][64];

    const int tid = threadIdx.x;
    const int bm0 = blockIdx.y * 64;
    const int bn0 = blockIdx.x * 64;

    const int lrow = tid >> 2;          // 0..63
    const int lc4  = (tid & 3) << 2;    // 0,4,8,12

    const int ty = tid >> 4;            // 0..15 -> m sub-tile
    const int tx = tid & 15;            // 0..15 -> n sub-tile

    float acc[4][4];
#pragma unroll
    for (int i = 0; i < 4; i++)
#pragma unroll
        for (int j = 0; j < 4; j++) acc[i][j] = 0.f;

    for (int k0 = 0; k0 < K; k0 += 16) {
        float4 a = *(const float4*)&A[(bm0 + lrow) * K + k0 + lc4];
        float4 b = *(const float4*)&B[(bn0 + lrow) * K + k0 + lc4];
        __syncthreads();
        sA[lc4 + 0][lrow] = a.x; sA[lc4 + 1][lrow] = a.y;
        sA[lc4 + 2][lrow] = a.z; sA[lc4 + 3][lrow] = a.w;
        sB[lc4 + 0][lrow] = b.x; sB[lc4 + 1][lrow] = b.y;
        sB[lc4 + 2][lrow] = b.z; sB[lc4 + 3][lrow] = b.w;
        __syncthreads();
#pragma unroll
        for (int kk = 0; kk < 16; kk++) {
            float4 ar = ((const float4*)&sA[kk][0])[ty];
            float4 br = ((const float4*)&sB[kk][0])[tx];
            float am[4] = {ar.x, ar.y, ar.z, ar.w};
            float bn[4] = {br.x, br.y, br.z, br.w};
#pragma unroll
            for (int i = 0; i < 4; i++)
#pragma unroll
                for (int j = 0; j < 4; j++) acc[i][j] = fmaf(am[i], bn[j], acc[i][j]);
        }
    }

#pragma unroll
    for (int i = 0; i < 4; i++) {
        float4 o = make_float4(acc[i][0], acc[i][1], acc[i][2], acc[i][3]);
        *(float4*)&C[(bm0 + ty * 4 + i) * N + bn0 + tx * 4] = o;
    }
}

// ---------------------------------------------------------------------------
// Fused energy + score + softmax. One block per (b,t) row. 256 threads.
// Thread tid handles s = tid + 256*j, j=0..3. MUFU.TANH-bound by design.
// ---------------------------------------------------------------------------
__device__ __forceinline__ float fast_tanh(float x) {
    float y;
    asm("tanh.approx.f32 %0, %1;" : "=f"(y) : "f"(x));
    return y;
}

__global__ void __launch_bounds__(256) attn_kernel(const float* __restrict__ v,
                                                   const float* __restrict__ vbias,
                                                   float* __restrict__ out) {
    const int bt = blockIdx.x;          // 0..1023
    const int b  = bt >> 8;
    const int tid = threadIdx.x;

    __shared__ float sq[HS];
    __shared__ float sv[HS];
    __shared__ float red[8];

    sq[tid] = g_q[bt * HS + tid];
    sv[tid] = v[tid];
    __syncthreads();

    const float vb = vbias[0];
    const float* __restrict__ kbase = g_k + (size_t)b * SRC * HS;

    float sc[4];
#pragma unroll
    for (int j = 0; j < 4; j++) {
        const int s = tid + (j << 8);
        const float4* __restrict__ krow = (const float4*)(kbase + (size_t)s * HS);
        float acc = 0.f;
#pragma unroll 8
        for (int h4 = 0; h4 < HS / 4; h4++) {
            float4 kv = krow[h4];
            float4 qv = ((const float4*)sq)[h4];
            float4 vv = ((const float4*)sv)[h4];
            float t0 = fast_tanh(qv.x + kv.x);
            float t1 = fast_tanh(qv.y + kv.y);
            float t2 = fast_tanh(qv.z + kv.z);
            float t3 = fast_tanh(qv.w + kv.w);
            acc = fmaf(vv.x, t0, acc);
            acc = fmaf(vv.y, t1, acc);
            acc = fmaf(vv.z, t2, acc);
            acc = fmaf(vv.w, t3, acc);
        }
        sc[j] = acc + vb;
    }

    // ---- block softmax over the 1024 scores (4 per thread) ----
    const int lane = tid & 31, wid = tid >> 5;

    float m = fmaxf(fmaxf(sc[0], sc[1]), fmaxf(sc[2], sc[3]));
#pragma unroll
    for (int o = 16; o > 0; o >>= 1) m = fmaxf(m, __shfl_xor_sync(0xffffffffu, m, o));
    if (lane == 0) red[wid] = m;
    __syncthreads();
    m = red[0];
#pragma unroll
    for (int i = 1; i < 8; i++) m = fmaxf(m, red[i]);
    __syncthreads();   // red reused below

    float e[4];
    float ssum = 0.f;
#pragma unroll
    for (int j = 0; j < 4; j++) { e[j] = __expf(sc[j] - m); ssum += e[j]; }
#pragma unroll
    for (int o = 16; o > 0; o >>= 1) ssum += __shfl_xor_sync(0xffffffffu, ssum, o);
    if (lane == 0) red[wid] = ssum;
    __syncthreads();
    float total = red[0];
#pragma unroll
    for (int i = 1; i < 8; i++) total += red[i];
    const float inv = __fdividef(1.0f, total);

    float* __restrict__ orow = out + (size_t)bt * SRC;
#pragma unroll
    for (int j = 0; j < 4; j++) orow[tid + (j << 8)] = e[j] * inv;
}

// ---------------------------------------------------------------------------
extern "C" void kernel_launch(void* const* d_in, const int* in_sizes, int n_in,
                              void* d_out, int out_size) {
    const float* query = (const float*)d_in[0];  // [4,256,256]
    const float* key   = (const float*)d_in[1];  // [4,1024,256]
    const float* Wq    = (const float*)d_in[2];  // [256,256]
    const float* Wk    = (const float*)d_in[3];  // [256,256]
    const float* v     = (const float*)d_in[4];  // [256]
    const float* vb    = (const float*)d_in[5];  // [1]
    float* out = (float*)d_out;                  // [4,256,1024]

    // q projection: M = 4*256 = 1024
    {
        dim3 grid(HS / 64, (BSZ * TGT) / 64);
        gemm_nt_kernel<<<grid, 256>>>(query, Wq, 0);
    }
    // k projection: M = 4*1024 = 4096
    {
        dim3 grid(HS / 64, (BSZ * SRC) / 64);
        gemm_nt_kernel<<<grid, 256>>>(key, Wk, 1);
    }
    // fused energy + softmax
    attn_kernel<<<BSZ * TGT, 256>>>(v, vb, out);
}

// round 4
// speedup vs baseline: 1.4865x; 1.4865x over previous
#include <cuda_runtime.h>

// Problem shape (fixed by the reference):
//   query [4,256,256], key [4,1024,256], Wq [256,256], Wk [256,256], v [256], v_bias [1]
//   out = softmax_s( sum_h v[h]*tanh(q[bt,h]+k[bs,h]) + vb )  -> [4,256,1024] fp32
#define BSZ 4
#define TGT 256
#define SRC 1024
#define HS  256

// Scratch for the projected q/k (allocation-free rule: __device__ globals).
__device__ __align__(16) float g_q[BSZ * TGT * HS];   // [1024, 256]
__device__ __align__(16) float g_k[BSZ * SRC * HS];   // [4096, 256]

// ---------------------------------------------------------------------------
// Fused NT GEMM for BOTH projections in one launch (fills the chip; the old
// q-only launch ran 64 blocks on 148 SMs -> occ 12%).
// Blocks [0,64):   g_q = query @ Wq^T   (M=1024)
// Blocks [64,320): g_k = key   @ Wk^T   (M=4096)
// BM=BN=64, BK=16, 256 threads, 4x4 per thread. N=K=256.
// ---------------------------------------------------------------------------
__global__ void __launch_bounds__(256) gemm_both_kernel(const float* __restrict__ query,
                                                        const float* __restrict__ key,
                                                        const float* __restrict__ Wq,
                                                        const float* __restrict__ Wk) {
    const int K = HS, N = HS;

    const float* __restrict__ A;
    const float* __restrict__ B;
    float* __restrict__ C;
    int local;
    if (blockIdx.x < 64) {            // q projection: 16 m-tiles x 4 n-tiles
        A = query; B = Wq; C = g_q; local = blockIdx.x;
    } else {                          // k projection: 64 m-tiles x 4 n-tiles
        A = key;   B = Wk; C = g_k; local = blockIdx.x - 64;
    }
    const int bm0 = (local >> 2) * 64;
    const int bn0 = (local & 3) * 64;

    __shared__ float sA[16][64];
    __shared__ float sB[16][64];

    const int tid = threadIdx.x;
    const int lrow = tid >> 2;          // 0..63
    const int lc4  = (tid & 3) << 2;    // 0,4,8,12
    const int ty = tid >> 4;            // 0..15 -> m sub-tile
    const int tx = tid & 15;            // 0..15 -> n sub-tile

    float acc[4][4];
#pragma unroll
    for (int i = 0; i < 4; i++)
#pragma unroll
        for (int j = 0; j < 4; j++) acc[i][j] = 0.f;

    for (int k0 = 0; k0 < K; k0 += 16) {
        float4 a = *(const float4*)&A[(bm0 + lrow) * K + k0 + lc4];
        float4 b = *(const float4*)&B[(bn0 + lrow) * K + k0 + lc4];
        __syncthreads();
        sA[lc4 + 0][lrow] = a.x; sA[lc4 + 1][lrow] = a.y;
        sA[lc4 + 2][lrow] = a.z; sA[lc4 + 3][lrow] = a.w;
        sB[lc4 + 0][lrow] = b.x; sB[lc4 + 1][lrow] = b.y;
        sB[lc4 + 2][lrow] = b.z; sB[lc4 + 3][lrow] = b.w;
        __syncthreads();
#pragma unroll
        for (int kk = 0; kk < 16; kk++) {
            float4 ar = ((const float4*)&sA[kk][0])[ty];
            float4 br = ((const float4*)&sB[kk][0])[tx];
            float am[4] = {ar.x, ar.y, ar.z, ar.w};
            float bn[4] = {br.x, br.y, br.z, br.w};
#pragma unroll
            for (int i = 0; i < 4; i++)
#pragma unroll
                for (int j = 0; j < 4; j++) acc[i][j] = fmaf(am[i], bn[j], acc[i][j]);
        }
    }

#pragma unroll
    for (int i = 0; i < 4; i++) {
        float4 o = make_float4(acc[i][0], acc[i][1], acc[i][2], acc[i][3]);
        *(float4*)&C[(bm0 + ty * 4 + i) * N + bn0 + tx * 4] = o;
    }
}

// ---------------------------------------------------------------------------
// Packed f32x2 helpers (Blackwell paired-FP32 PTX; exact fp32 semantics).
// ---------------------------------------------------------------------------
typedef unsigned long long u64t;

__device__ __forceinline__ u64t f2pack(float lo, float hi) {
    u64t r; asm("mov.b64 %0, {%1, %2};" : "=l"(r) : "f"(lo), "f"(hi)); return r;
}
__device__ __forceinline__ void f2unpack(u64t p, float& lo, float& hi) {
    asm("mov.b64 {%0, %1}, %2;" : "=f"(lo), "=f"(hi) : "l"(p));
}
__device__ __forceinline__ u64t f2add(u64t a, u64t b) {
    u64t r; asm("add.rn.f32x2 %0, %1, %2;" : "=l"(r) : "l"(a), "l"(b)); return r;
}
__device__ __forceinline__ u64t f2fma(u64t a, u64t b, u64t c) {
    u64t r; asm("fma.rn.f32x2 %0, %1, %2, %3;" : "=l"(r) : "l"(a), "l"(b), "l"(c)); return r;
}
__device__ __forceinline__ float fast_tanh(float x) {
    float y; asm("tanh.approx.f32 %0, %1;" : "=f"(y) : "f"(x)); return y;
}

// ---------------------------------------------------------------------------
// Fused energy + score + softmax. One block per (b,t) row. 256 threads.
// Thread tid handles s in {tid, tid+256, tid+512, tid+768}. All 4 s-rows are
// processed in one h-sweep so the q/v shared loads are amortized 4x, and the
// FADD/FFMA work runs on packed f32x2 (half the issue slots, exact fp32).
// ---------------------------------------------------------------------------
__global__ void __launch_bounds__(256) attn_kernel(const float* __restrict__ v,
                                                   const float* __restrict__ vbias,
                                                   float* __restrict__ out) {
    const int bt = blockIdx.x;          // 0..1023
    const int b  = bt >> 8;
    const int tid = threadIdx.x;

    __shared__ float sq[HS];
    __shared__ float sv[HS];
    __shared__ float red[8];

    sq[tid] = g_q[bt * HS + tid];
    sv[tid] = v[tid];
    __syncthreads();

    const float vb = vbias[0];
    const float* __restrict__ kbase = g_k + (size_t)b * SRC * HS;

    const float4* __restrict__ krow0 = (const float4*)(kbase + (size_t)(tid        ) * HS);
    const float4* __restrict__ krow1 = (const float4*)(kbase + (size_t)(tid + 256  ) * HS);
    const float4* __restrict__ krow2 = (const float4*)(kbase + (size_t)(tid + 512  ) * HS);
    const float4* __restrict__ krow3 = (const float4*)(kbase + (size_t)(tid + 768  ) * HS);

    u64t accA[4], accB[4];              // per-s packed pair accumulators
#pragma unroll
    for (int j = 0; j < 4; j++) { accA[j] = f2pack(0.f, 0.f); accB[j] = f2pack(0.f, 0.f); }

#pragma unroll 2
    for (int h4 = 0; h4 < HS / 4; h4++) {
        float4 qv = ((const float4*)sq)[h4];
        float4 vv = ((const float4*)sv)[h4];
        u64t qxy = f2pack(qv.x, qv.y), qzw = f2pack(qv.z, qv.w);
        u64t vxy = f2pack(vv.x, vv.y), vzw = f2pack(vv.z, vv.w);

        float4 kv0 = krow0[h4];
        float4 kv1 = krow1[h4];
        float4 kv2 = krow2[h4];
        float4 kv3 = krow3[h4];

#pragma unroll
        for (int j = 0; j < 4; j++) {
            float4 kv = (j == 0) ? kv0 : (j == 1) ? kv1 : (j == 2) ? kv2 : kv3;
            u64t sxy = f2add(qxy, f2pack(kv.x, kv.y));
            u64t szw = f2add(qzw, f2pack(kv.z, kv.w));
            float x0, x1, x2, x3;
            f2unpack(sxy, x0, x1);
            f2unpack(szw, x2, x3);
            float t0 = fast_tanh(x0), t1 = fast_tanh(x1);
            float t2 = fast_tanh(x2), t3 = fast_tanh(x3);
            accA[j] = f2fma(vxy, f2pack(t0, t1), accA[j]);
            accB[j] = f2fma(vzw, f2pack(t2, t3), accB[j]);
        }
    }

    float sc[4];
#pragma unroll
    for (int j = 0; j < 4; j++) {
        float a0, a1, b0, b1;
        f2unpack(accA[j], a0, a1);
        f2unpack(accB[j], b0, b1);
        sc[j] = (a0 + a1) + (b0 + b1) + vb;
    }

    // ---- block softmax over the 1024 scores (4 per thread) ----
    const int lane = tid & 31, wid = tid >> 5;

    float m = fmaxf(fmaxf(sc[0], sc[1]), fmaxf(sc[2], sc[3]));
#pragma unroll
    for (int o = 16; o > 0; o >>= 1) m = fmaxf(m, __shfl_xor_sync(0xffffffffu, m, o));
    if (lane == 0) red[wid] = m;
    __syncthreads();
    m = red[0];
#pragma unroll
    for (int i = 1; i < 8; i++) m = fmaxf(m, red[i]);
    __syncthreads();   // red reused below

    float e[4];
    float ssum = 0.f;
#pragma unroll
    for (int j = 0; j < 4; j++) { e[j] = __expf(sc[j] - m); ssum += e[j]; }
#pragma unroll
    for (int o = 16; o > 0; o >>= 1) ssum += __shfl_xor_sync(0xffffffffu, ssum, o);
    if (lane == 0) red[wid] = ssum;
    __syncthreads();
    float total = red[0];
#pragma unroll
    for (int i = 1; i < 8; i++) total += red[i];
    const float inv = __fdividef(1.0f, total);

    float* __restrict__ orow = out + (size_t)bt * SRC;
#pragma unroll
    for (int j = 0; j < 4; j++) orow[tid + (j << 8)] = e[j] * inv;
}

// ---------------------------------------------------------------------------
extern "C" void kernel_launch(void* const* d_in, const int* in_sizes, int n_in,
                              void* d_out, int out_size) {
    const float* query = (const float*)d_in[0];  // [4,256,256]
    const float* key   = (const float*)d_in[1];  // [4,1024,256]
    const float* Wq    = (const float*)d_in[2];  // [256,256]
    const float* Wk    = (const float*)d_in[3];  // [256,256]
    const float* v     = (const float*)d_in[4];  // [256]
    const float* vb    = (const float*)d_in[5];  // [1]
    float* out = (float*)d_out;                  // [4,256,1024]

    gemm_both_kernel<<<320, 256>>>(query, key, Wq, Wk);
    attn_kernel<<<BSZ * TGT, 256>>>(v, vb, out);
}

// round 5
// speedup vs baseline: 1.4943x; 1.0052x over previous
#include <cuda_runtime.h>
#include <math_constants.h>

// Problem shape (fixed by the reference):
//   query [4,256,256], key [4,1024,256], Wq [256,256], Wk [256,256], v [256], v_bias [1]
//   out = softmax_s( sum_h v[h]*tanh(q[bt,h]+k[bs,h]) + vb )  -> [4,256,1024] fp32
#define BSZ 4
#define TGT 256
#define SRC 1024
#define HS  256

__device__ __align__(16) float g_q[BSZ * TGT * HS];   // [1024, 256]
__device__ __align__(16) float g_k[BSZ * SRC * HS];   // [4096, 256]

// ---------------------------------------------------------------------------
// Fused NT GEMM for both projections, one launch (320 blocks fills the chip).
// Blocks [0,64): g_q = query @ Wq^T.  Blocks [64,320): g_k = key @ Wk^T.
// BM=BN=64, BK=16, 256 threads, 4x4 per thread. N=K=256.
// ---------------------------------------------------------------------------
__global__ void __launch_bounds__(256) gemm_both_kernel(const float* __restrict__ query,
                                                        const float* __restrict__ key,
                                                        const float* __restrict__ Wq,
                                                        const float* __restrict__ Wk) {
    const int K = HS, N = HS;

    const float* __restrict__ A;
    const float* __restrict__ B;
    float* __restrict__ C;
    int local;
    if (blockIdx.x < 64) { A = query; B = Wq; C = g_q; local = blockIdx.x; }
    else                 { A = key;   B = Wk; C = g_k; local = blockIdx.x - 64; }
    const int bm0 = (local >> 2) * 64;
    const int bn0 = (local & 3) * 64;

    __shared__ float sA[16][64];
    __shared__ float sB[16][64];

    const int tid = threadIdx.x;
    const int lrow = tid >> 2;
    const int lc4  = (tid & 3) << 2;
    const int ty = tid >> 4;
    const int tx = tid & 15;

    float acc[4][4];
#pragma unroll
    for (int i = 0; i < 4; i++)
#pragma unroll
        for (int j = 0; j < 4; j++) acc[i][j] = 0.f;

    for (int k0 = 0; k0 < K; k0 += 16) {
        float4 a = *(const float4*)&A[(bm0 + lrow) * K + k0 + lc4];
        float4 b = *(const float4*)&B[(bn0 + lrow) * K + k0 + lc4];
        __syncthreads();
        sA[lc4 + 0][lrow] = a.x; sA[lc4 + 1][lrow] = a.y;
        sA[lc4 + 2][lrow] = a.z; sA[lc4 + 3][lrow] = a.w;
        sB[lc4 + 0][lrow] = b.x; sB[lc4 + 1][lrow] = b.y;
        sB[lc4 + 2][lrow] = b.z; sB[lc4 + 3][lrow] = b.w;
        __syncthreads();
#pragma unroll
        for (int kk = 0; kk < 16; kk++) {
            float4 ar = ((const float4*)&sA[kk][0])[ty];
            float4 br = ((const float4*)&sB[kk][0])[tx];
            float am[4] = {ar.x, ar.y, ar.z, ar.w};
            float bn[4] = {br.x, br.y, br.z, br.w};
#pragma unroll
            for (int i = 0; i < 4; i++)
#pragma unroll
                for (int j = 0; j < 4; j++) acc[i][j] = fmaf(am[i], bn[j], acc[i][j]);
        }
    }

#pragma unroll
    for (int i = 0; i < 4; i++) {
        float4 o = make_float4(acc[i][0], acc[i][1], acc[i][2], acc[i][3]);
        *(float4*)&C[(bm0 + ty * 4 + i) * N + bn0 + tx * 4] = o;
    }
}

// ---------------------------------------------------------------------------
// Packed f32x2 helpers (exact fp32 semantics) + fast tanh.
// ---------------------------------------------------------------------------
typedef unsigned long long u64t;

__device__ __forceinline__ u64t f2pack(float lo, float hi) {
    u64t r; asm("mov.b64 %0, {%1, %2};" : "=l"(r) : "f"(lo), "f"(hi)); return r;
}
__device__ __forceinline__ void f2unpack(u64t p, float& lo, float& hi) {
    asm("mov.b64 {%0, %1}, %2;" : "=f"(lo), "=f"(hi) : "l"(p));
}
__device__ __forceinline__ u64t f2add(u64t a, u64t b) {
    u64t r; asm("add.rn.f32x2 %0, %1, %2;" : "=l"(r) : "l"(a), "l"(b)); return r;
}
__device__ __forceinline__ u64t f2fma(u64t a, u64t b, u64t c) {
    u64t r; asm("fma.rn.f32x2 %0, %1, %2, %3;" : "=l"(r) : "l"(a), "l"(b), "l"(c)); return r;
}
__device__ __forceinline__ float fast_tanh(float x) {
    float y; asm("tanh.approx.f32 %0, %1;" : "=f"(y) : "f"(x)); return y;
}

// One k-row dot: lane holds q/v pairs for h = {4l..4l+3, 128+4l..128+4l+3}.
// Returns this lane's partial sum for the row.
__device__ __forceinline__ float row_partial(float4 k0, float4 k1,
                                             u64t qp0, u64t qp1, u64t qp2, u64t qp3,
                                             u64t vp0, u64t vp1, u64t vp2, u64t vp3) {
    u64t p0 = f2add(qp0, f2pack(k0.x, k0.y));
    u64t p1 = f2add(qp1, f2pack(k0.z, k0.w));
    u64t p2 = f2add(qp2, f2pack(k1.x, k1.y));
    u64t p3 = f2add(qp3, f2pack(k1.z, k1.w));
    float x0, x1, x2, x3, x4, x5, x6, x7;
    f2unpack(p0, x0, x1); f2unpack(p1, x2, x3);
    f2unpack(p2, x4, x5); f2unpack(p3, x6, x7);
    u64t acc = f2fma(vp0, f2pack(fast_tanh(x0), fast_tanh(x1)),
               f2fma(vp1, f2pack(fast_tanh(x2), fast_tanh(x3)),
               f2fma(vp2, f2pack(fast_tanh(x4), fast_tanh(x5)),
               f2fma(vp3, f2pack(fast_tanh(x6), fast_tanh(x7)), f2pack(0.f, 0.f)))));
    float alo, ahi;
    f2unpack(acc, alo, ahi);
    return alo + ahi;
}

// ---------------------------------------------------------------------------
// Warp-per-(b,t): lanes split h (coalesced LDG.128 on k), butterfly-reduce per
// s-row, scores staged in smem, per-warp softmax. grid=512, block=64 (2 warps).
// ---------------------------------------------------------------------------
__global__ void __launch_bounds__(64) attn_kernel(const float* __restrict__ v,
                                                  const float* __restrict__ vbias,
                                                  float* __restrict__ out) {
    const int w    = threadIdx.x >> 5;
    const int lane = threadIdx.x & 31;
    const int bt   = blockIdx.x * 2 + w;       // 0..1023
    const int b    = bt >> 8;

    __shared__ float scores[2][SRC];

    // q, v resident in registers for the whole warp lifetime.
    const float4* __restrict__ q4 = (const float4*)(g_q + (size_t)bt * HS);
    const float4* __restrict__ v4 = (const float4*)v;
    float4 q0 = q4[lane], q1 = q4[32 + lane];
    float4 vv0 = v4[lane], vv1 = v4[32 + lane];
    u64t qp0 = f2pack(q0.x, q0.y),  qp1 = f2pack(q0.z, q0.w);
    u64t qp2 = f2pack(q1.x, q1.y),  qp3 = f2pack(q1.z, q1.w);
    u64t vp0 = f2pack(vv0.x, vv0.y), vp1 = f2pack(vv0.z, vv0.w);
    u64t vp2 = f2pack(vv1.x, vv1.y), vp3 = f2pack(vv1.z, vv1.w);
    const float vb = vbias[0];

    const float4* __restrict__ kb = (const float4*)(g_k + (size_t)b * SRC * HS);

    // Main loop: 2 s-rows per iteration for ILP (independent tanh/fma chains).
    for (int s = 0; s < SRC; s += 2) {
        const float4* kr0 = kb + (size_t)s * (HS / 4);
        const float4* kr1 = kr0 + (HS / 4);
        float4 a0 = kr0[lane], a1 = kr0[32 + lane];
        float4 b0 = kr1[lane], b1 = kr1[32 + lane];

        float sA = row_partial(a0, a1, qp0, qp1, qp2, qp3, vp0, vp1, vp2, vp3);
        float sB = row_partial(b0, b1, qp0, qp1, qp2, qp3, vp0, vp1, vp2, vp3);

#pragma unroll
        for (int o = 16; o > 0; o >>= 1) {
            sA += __shfl_xor_sync(0xffffffffu, sA, o);
            sB += __shfl_xor_sync(0xffffffffu, sB, o);
        }
        if (lane == 0) {
            scores[w][s]     = sA + vb;
            scores[w][s + 1] = sB + vb;
        }
    }
    __syncwarp();

    // Per-warp softmax over 1024 scores: 32 per lane, coalesced LDS/STG.
    float x[32];
    float m = -CUDART_INF_F;
#pragma unroll
    for (int i = 0; i < 32; i++) {
        x[i] = scores[w][i * 32 + lane];
        m = fmaxf(m, x[i]);
    }
#pragma unroll
    for (int o = 16; o > 0; o >>= 1) m = fmaxf(m, __shfl_xor_sync(0xffffffffu, m, o));

    float ssum = 0.f;
#pragma unroll
    for (int i = 0; i < 32; i++) { x[i] = __expf(x[i] - m); ssum += x[i]; }
#pragma unroll
    for (int o = 16; o > 0; o >>= 1) ssum += __shfl_xor_sync(0xffffffffu, ssum, o);
    const float inv = __fdividef(1.0f, ssum);

    float* __restrict__ orow = out + (size_t)bt * SRC;
#pragma unroll
    for (int i = 0; i < 32; i++) orow[i * 32 + lane] = x[i] * inv;
}

// ---------------------------------------------------------------------------
extern "C" void kernel_launch(void* const* d_in, const int* in_sizes, int n_in,
                              void* d_out, int out_size) {
    const float* query = (const float*)d_in[0];  // [4,256,256]
    const float* key   = (const float*)d_in[1];  // [4,1024,256]
    const float* Wq    = (const float*)d_in[2];  // [256,256]
    const float* Wk    = (const float*)d_in[3];  // [256,256]
    const float* v     = (const float*)d_in[4];  // [256]
    const float* vb    = (const float*)d_in[5];  // [1]
    float* out = (float*)d_out;                  // [4,256,1024]

    gemm_both_kernel<<<320, 256>>>(query, key, Wq, Wk);
    attn_kernel<<<BSZ * TGT / 2, 64>>>(v, vb, out);
}

// round 6
// speedup vs baseline: 3.5803x; 2.3960x over previous
#include <cuda_runtime.h>

// Problem shape (fixed by the reference):
//   query [4,256,256], key [4,1024,256], Wq [256,256], Wk [256,256], v [256], v_bias [1]
//   out = softmax_s( sum_h v[h]*tanh(q[bt,h]+k[bs,h]) + vb )  -> [4,256,1024] fp32
#define BSZ 4
#define TGT 256
#define SRC 1024
#define HS  256

__device__ __align__(16) float g_q[BSZ * TGT * HS];    // [1024, 256]  (bt-major)
__device__ __align__(16) float g_kT[BSZ * HS * SRC];   // [4, 256 h, 1024 s]  TRANSPOSED

// ---------------------------------------------------------------------------
// Fused NT GEMM, one launch (320 blocks).
// Blocks [0,64):   g_q  = query @ Wq^T      (row-major store)
// Blocks [64,320): g_kT = (key @ Wk^T)^T    (transposed scalar store, h-major)
// BM=BN=64, BK=16, 256 threads, 4x4 per thread. N=K=256.
// ---------------------------------------------------------------------------
__global__ void __launch_bounds__(256) gemm_both_kernel(const float* __restrict__ query,
                                                        const float* __restrict__ key,
                                                        const float* __restrict__ Wq,
                                                        const float* __restrict__ Wk) {
    const int K = HS, N = HS;

    const float* __restrict__ A;
    const float* __restrict__ B;
    int local;
    const bool is_q = blockIdx.x < 64;
    if (is_q) { A = query; B = Wq; local = blockIdx.x; }
    else      { A = key;   B = Wk; local = blockIdx.x - 64; }
    const int bm0 = (local >> 2) * 64;
    const int bn0 = (local & 3) * 64;

    __shared__ float sA[16][64];
    __shared__ float sB[16][64];

    const int tid = threadIdx.x;
    const int lrow = tid >> 2;
    const int lc4  = (tid & 3) << 2;
    const int ty = tid >> 4;
    const int tx = tid & 15;

    float acc[4][4];
#pragma unroll
    for (int i = 0; i < 4; i++)
#pragma unroll
        for (int j = 0; j < 4; j++) acc[i][j] = 0.f;

    for (int k0 = 0; k0 < K; k0 += 16) {
        float4 a = *(const float4*)&A[(bm0 + lrow) * K + k0 + lc4];
        float4 b = *(const float4*)&B[(bn0 + lrow) * K + k0 + lc4];
        __syncthreads();
        sA[lc4 + 0][lrow] = a.x; sA[lc4 + 1][lrow] = a.y;
        sA[lc4 + 2][lrow] = a.z; sA[lc4 + 3][lrow] = a.w;
        sB[lc4 + 0][lrow] = b.x; sB[lc4 + 1][lrow] = b.y;
        sB[lc4 + 2][lrow] = b.z; sB[lc4 + 3][lrow] = b.w;
        __syncthreads();
#pragma unroll
        for (int kk = 0; kk < 16; kk++) {
            float4 ar = ((const float4*)&sA[kk][0])[ty];
            float4 br = ((const float4*)&sB[kk][0])[tx];
            float am[4] = {ar.x, ar.y, ar.z, ar.w};
            float bn[4] = {br.x, br.y, br.z, br.w};
#pragma unroll
            for (int i = 0; i < 4; i++)
#pragma unroll
                for (int j = 0; j < 4; j++) acc[i][j] = fmaf(am[i], bn[j], acc[i][j]);
        }
    }

    if (is_q) {
#pragma unroll
        for (int i = 0; i < 4; i++) {
            float4 o = make_float4(acc[i][0], acc[i][1], acc[i][2], acc[i][3]);
            *(float4*)&g_q[(bm0 + ty * 4 + i) * N + bn0 + tx * 4] = o;
        }
    } else {
        // transposed store: C[m][n] -> g_kT[b][h=n][s=m%1024]
#pragma unroll
        for (int i = 0; i < 4; i++) {
            const int m = bm0 + ty * 4 + i;
            const int bb = m >> 10;
            const int s  = m & (SRC - 1);
#pragma unroll
            for (int j = 0; j < 4; j++) {
                const int h = bn0 + tx * 4 + j;
                g_kT[((size_t)bb * HS + h) * SRC + s] = acc[i][j];
            }
        }
    }
}

// ---------------------------------------------------------------------------
// Packed f32x2 helpers (exact fp32 semantics) + fast tanh.
// ---------------------------------------------------------------------------
typedef unsigned long long u64t;

__device__ __forceinline__ u64t f2pack(float lo, float hi) {
    u64t r; asm("mov.b64 %0, {%1, %2};" : "=l"(r) : "f"(lo), "f"(hi)); return r;
}
__device__ __forceinline__ void f2unpack(u64t p, float& lo, float& hi) {
    asm("mov.b64 {%0, %1}, %2;" : "=f"(lo), "=f"(hi) : "l"(p));
}
__device__ __forceinline__ u64t f2add(u64t a, u64t b) {
    u64t r; asm("add.rn.f32x2 %0, %1, %2;" : "=l"(r) : "l"(a), "l"(b)); return r;
}
__device__ __forceinline__ u64t f2fma(u64t a, u64t b, u64t c) {
    u64t r; asm("fma.rn.f32x2 %0, %1, %2, %3;" : "=l"(r) : "l"(a), "l"(b), "l"(c)); return r;
}
__device__ __forceinline__ float fast_tanh(float x) {
    float y; asm("tanh.approx.f32 %0, %1;" : "=f"(y) : "f"(x)); return y;
}

// ---------------------------------------------------------------------------
// Fused energy + softmax. Block per (b,t), 256 threads; thread owns the 4
// CONSECUTIVE s in [4*tid, 4*tid+4). Inner loop over h reads kT[h][4tid..]:
// warp-LDG = 512 contiguous bytes (minimum wavefronts), no shuffles, private
// accumulators -> high occupancy + ILP. MUFU.TANH-bound by design.
// ---------------------------------------------------------------------------
__global__ void __launch_bounds__(256) attn_kernel(const float* __restrict__ v,
                                                   const float* __restrict__ vbias,
                                                   float* __restrict__ out) {
    const int bt = blockIdx.x;          // 0..1023
    const int b  = bt >> 8;
    const int tid = threadIdx.x;

    __shared__ float sq[HS];
    __shared__ float sv[HS];
    __shared__ float red[8];

    sq[tid] = g_q[bt * HS + tid];
    sv[tid] = v[tid];
    __syncthreads();

    const float4* __restrict__ kT = (const float4*)(g_kT + (size_t)b * HS * SRC);

    u64t acc01 = f2pack(0.f, 0.f);
    u64t acc23 = f2pack(0.f, 0.f);

    for (int h4 = 0; h4 < HS / 4; h4++) {
        float4 qv = ((const float4*)sq)[h4];
        float4 vv = ((const float4*)sv)[h4];
        // 4 independent k loads (MLP) for h = 4*h4 .. 4*h4+3
        float4 k0 = kT[(h4 * 4 + 0) * (SRC / 4) + tid];
        float4 k1 = kT[(h4 * 4 + 1) * (SRC / 4) + tid];
        float4 k2 = kT[(h4 * 4 + 2) * (SRC / 4) + tid];
        float4 k3 = kT[(h4 * 4 + 3) * (SRC / 4) + tid];

#pragma unroll
        for (int u = 0; u < 4; u++) {
            float4 kv = (u == 0) ? k0 : (u == 1) ? k1 : (u == 2) ? k2 : k3;
            const float qh = (u == 0) ? qv.x : (u == 1) ? qv.y : (u == 2) ? qv.z : qv.w;
            const float vh = (u == 0) ? vv.x : (u == 1) ? vv.y : (u == 2) ? vv.z : vv.w;
            u64t qq = f2pack(qh, qh);
            u64t vv2 = f2pack(vh, vh);
            u64t s01 = f2add(qq, f2pack(kv.x, kv.y));
            u64t s23 = f2add(qq, f2pack(kv.z, kv.w));
            float x0, x1, x2, x3;
            f2unpack(s01, x0, x1);
            f2unpack(s23, x2, x3);
            acc01 = f2fma(vv2, f2pack(fast_tanh(x0), fast_tanh(x1)), acc01);
            acc23 = f2fma(vv2, f2pack(fast_tanh(x2), fast_tanh(x3)), acc23);
        }
    }

    const float vb = vbias[0];
    float sc[4];
    f2unpack(acc01, sc[0], sc[1]);
    f2unpack(acc23, sc[2], sc[3]);
#pragma unroll
    for (int j = 0; j < 4; j++) sc[j] += vb;

    // ---- block softmax over the 1024 scores (4 consecutive per thread) ----
    const int lane = tid & 31, wid = tid >> 5;

    float m = fmaxf(fmaxf(sc[0], sc[1]), fmaxf(sc[2], sc[3]));
#pragma unroll
    for (int o = 16; o > 0; o >>= 1) m = fmaxf(m, __shfl_xor_sync(0xffffffffu, m, o));
    if (lane == 0) red[wid] = m;
    __syncthreads();
    m = red[0];
#pragma unroll
    for (int i = 1; i < 8; i++) m = fmaxf(m, red[i]);
    __syncthreads();   // red reused below

    float e[4];
    float ssum = 0.f;
#pragma unroll
    for (int j = 0; j < 4; j++) { e[j] = __expf(sc[j] - m); ssum += e[j]; }
#pragma unroll
    for (int o = 16; o > 0; o >>= 1) ssum += __shfl_xor_sync(0xffffffffu, ssum, o);
    if (lane == 0) red[wid] = ssum;
    __syncthreads();
    float total = red[0];
#pragma unroll
    for (int i = 1; i < 8; i++) total += red[i];
    const float inv = __fdividef(1.0f, total);

    float4 o4 = make_float4(e[0] * inv, e[1] * inv, e[2] * inv, e[3] * inv);
    *(float4*)(out + (size_t)bt * SRC + tid * 4) = o4;
}

// ---------------------------------------------------------------------------
extern "C" void kernel_launch(void* const* d_in, const int* in_sizes, int n_in,
                              void* d_out, int out_size) {
    const float* query = (const float*)d_in[0];  // [4,256,256]
    const float* key   = (const float*)d_in[1];  // [4,1024,256]
    const float* Wq    = (const float*)d_in[2];  // [256,256]
    const float* Wk    = (const float*)d_in[3];  // [256,256]
    const float* v     = (const float*)d_in[4];  // [256]
    const float* vb    = (const float*)d_in[5];  // [1]
    float* out = (float*)d_out;                  // [4,256,1024]

    gemm_both_kernel<<<320, 256>>>(query, key, Wq, Wk);
    attn_kernel<<<BSZ * TGT, 256>>>(v, vb, out);
}

// round 7
// speedup vs baseline: 3.8398x; 1.0725x over previous
#include <cuda_runtime.h>
#include <cuda_fp16.h>

// Problem shape (fixed by the reference):
//   query [4,256,256], key [4,1024,256], Wq [256,256], Wk [256,256], v [256], v_bias [1]
//   out = softmax_s( sum_h v[h]*tanh(q[bt,h]+k[bs,h]) + vb )  -> [4,256,1024] fp32
#define BSZ 4
#define TGT 256
#define SRC 1024
#define HS  256

__device__ __align__(16) float  g_q[BSZ * TGT * HS];     // [1024, 256] fp32
__device__ __align__(16) __half g_kT16[BSZ * HS * SRC];  // [4, 256 h, 1024 s] fp16, TRANSPOSED

// ---------------------------------------------------------------------------
// Fused NT GEMM, one launch (320 blocks).
// Blocks [0,64):   g_q    = query @ Wq^T                (fp32 row-major)
// Blocks [64,320): g_kT16 = half((key @ Wk^T)^T)        (fp16, h-major)
// BM=BN=64, BK=16, 256 threads, 4x4 per thread. N=K=256.
// ---------------------------------------------------------------------------
__global__ void __launch_bounds__(256) gemm_both_kernel(const float* __restrict__ query,
                                                        const float* __restrict__ key,
                                                        const float* __restrict__ Wq,
                                                        const float* __restrict__ Wk) {
    const int K = HS, N = HS;

    const float* __restrict__ A;
    const float* __restrict__ B;
    int local;
    const bool is_q = blockIdx.x < 64;
    if (is_q) { A = query; B = Wq; local = blockIdx.x; }
    else      { A = key;   B = Wk; local = blockIdx.x - 64; }
    const int bm0 = (local >> 2) * 64;
    const int bn0 = (local & 3) * 64;

    __shared__ float sA[16][64];
    __shared__ float sB[16][64];

    const int tid = threadIdx.x;
    const int lrow = tid >> 2;
    const int lc4  = (tid & 3) << 2;
    const int ty = tid >> 4;
    const int tx = tid & 15;

    float acc[4][4];
#pragma unroll
    for (int i = 0; i < 4; i++)
#pragma unroll
        for (int j = 0; j < 4; j++) acc[i][j] = 0.f;

    for (int k0 = 0; k0 < K; k0 += 16) {
        float4 a = *(const float4*)&A[(bm0 + lrow) * K + k0 + lc4];
        float4 b = *(const float4*)&B[(bn0 + lrow) * K + k0 + lc4];
        __syncthreads();
        sA[lc4 + 0][lrow] = a.x; sA[lc4 + 1][lrow] = a.y;
        sA[lc4 + 2][lrow] = a.z; sA[lc4 + 3][lrow] = a.w;
        sB[lc4 + 0][lrow] = b.x; sB[lc4 + 1][lrow] = b.y;
        sB[lc4 + 2][lrow] = b.z; sB[lc4 + 3][lrow] = b.w;
        __syncthreads();
#pragma unroll
        for (int kk = 0; kk < 16; kk++) {
            float4 ar = ((const float4*)&sA[kk][0])[ty];
            float4 br = ((const float4*)&sB[kk][0])[tx];
            float am[4] = {ar.x, ar.y, ar.z, ar.w};
            float bn[4] = {br.x, br.y, br.z, br.w};
#pragma unroll
            for (int i = 0; i < 4; i++)
#pragma unroll
                for (int j = 0; j < 4; j++) acc[i][j] = fmaf(am[i], bn[j], acc[i][j]);
        }
    }

    if (is_q) {
#pragma unroll
        for (int i = 0; i < 4; i++) {
            float4 o = make_float4(acc[i][0], acc[i][1], acc[i][2], acc[i][3]);
            *(float4*)&g_q[(bm0 + ty * 4 + i) * N + bn0 + tx * 4] = o;
        }
    } else {
        // transposed fp16 store: C[m][n] -> g_kT16[b][h=n][s=m%1024]
#pragma unroll
        for (int i = 0; i < 4; i++) {
            const int m = bm0 + ty * 4 + i;
            const int bb = m >> 10;
            const int s  = m & (SRC - 1);
#pragma unroll
            for (int j = 0; j < 4; j++) {
                const int h = bn0 + tx * 4 + j;
                g_kT16[((size_t)bb * HS + h) * SRC + s] = __float2half_rn(acc[i][j]);
            }
        }
    }
}

// ---------------------------------------------------------------------------
// half2 tanh
// ---------------------------------------------------------------------------
__device__ __forceinline__ __half2 tanh_h2(__half2 x) {
    __half2 y;
    asm("tanh.approx.f16x2 %0, %1;"
        : "=r"(*(unsigned int*)&y) : "r"(*(const unsigned int*)&x));
    return y;
}

// ---------------------------------------------------------------------------
// Fused energy + softmax. Block per (b,t), 256 threads; thread owns the 4
// CONSECUTIVE s in [4*tid, 4*tid+4). Energy math in half2 (HADD2 / MUFU.TANH
// f16x2 / HFMA2), with fp32 re-accumulation every 16 h to bound rounding.
// ---------------------------------------------------------------------------
__global__ void __launch_bounds__(256) attn_kernel(const float* __restrict__ v,
                                                   const float* __restrict__ vbias,
                                                   float* __restrict__ out) {
    const int bt = blockIdx.x;          // 0..1023
    const int b  = bt >> 8;
    const int tid = threadIdx.x;

    __shared__ float sq[HS];
    __shared__ float sv[HS];
    __shared__ float red[8];

    sq[tid] = g_q[bt * HS + tid];
    sv[tid] = v[tid];
    __syncthreads();

    const __half* __restrict__ kT = g_kT16 + (size_t)b * HS * SRC;

    float f0 = 0.f, f1 = 0.f, f2 = 0.f, f3 = 0.f;   // fp32 master accumulators

    for (int c = 0; c < 16; c++) {                   // 16 chunks of 16 h
        __half2 a01 = __float2half2_rn(0.f);
        __half2 a23 = __float2half2_rn(0.f);
#pragma unroll
        for (int u4 = 0; u4 < 4; u4++) {             // 4 h4-steps per chunk
            const int h4 = c * 4 + u4;
            float4 qv = ((const float4*)sq)[h4];
            float4 vv = ((const float4*)sv)[h4];
            // 4 h-rows, 4 consecutive s per thread: uint2 = 4 halves (8B).
            uint2 k0 = ((const uint2*)(kT + (size_t)(h4 * 4 + 0) * SRC))[tid];
            uint2 k1 = ((const uint2*)(kT + (size_t)(h4 * 4 + 1) * SRC))[tid];
            uint2 k2 = ((const uint2*)(kT + (size_t)(h4 * 4 + 2) * SRC))[tid];
            uint2 k3 = ((const uint2*)(kT + (size_t)(h4 * 4 + 3) * SRC))[tid];
#pragma unroll
            for (int u = 0; u < 4; u++) {
                uint2 kk = (u == 0) ? k0 : (u == 1) ? k1 : (u == 2) ? k2 : k3;
                const float qh = (u == 0) ? qv.x : (u == 1) ? qv.y : (u == 2) ? qv.z : qv.w;
                const float vh = (u == 0) ? vv.x : (u == 1) ? vv.y : (u == 2) ? vv.z : vv.w;
                __half2 q2 = __float2half2_rn(qh);
                __half2 v2 = __float2half2_rn(vh);
                __half2 k01 = *(__half2*)&kk.x;
                __half2 k23 = *(__half2*)&kk.y;
                __half2 t01 = tanh_h2(__hadd2(q2, k01));
                __half2 t23 = tanh_h2(__hadd2(q2, k23));
                a01 = __hfma2(v2, t01, a01);
                a23 = __hfma2(v2, t23, a23);
            }
        }
        float2 p01 = __half22float2(a01);
        float2 p23 = __half22float2(a23);
        f0 += p01.x; f1 += p01.y; f2 += p23.x; f3 += p23.y;
    }

    const float vb = vbias[0];
    float sc[4] = { f0 + vb, f1 + vb, f2 + vb, f3 + vb };

    // ---- block softmax over the 1024 scores (4 consecutive per thread) ----
    const int lane = tid & 31, wid = tid >> 5;

    float m = fmaxf(fmaxf(sc[0], sc[1]), fmaxf(sc[2], sc[3]));
#pragma unroll
    for (int o = 16; o > 0; o >>= 1) m = fmaxf(m, __shfl_xor_sync(0xffffffffu, m, o));
    if (lane == 0) red[wid] = m;
    __syncthreads();
    m = red[0];
#pragma unroll
    for (int i = 1; i < 8; i++) m = fmaxf(m, red[i]);
    __syncthreads();   // red reused below

    float e[4];
    float ssum = 0.f;
#pragma unroll
    for (int j = 0; j < 4; j++) { e[j] = __expf(sc[j] - m); ssum += e[j]; }
#pragma unroll
    for (int o = 16; o > 0; o >>= 1) ssum += __shfl_xor_sync(0xffffffffu, ssum, o);
    if (lane == 0) red[wid] = ssum;
    __syncthreads();
    float total = red[0];
#pragma unroll
    for (int i = 1; i < 8; i++) total += red[i];
    const float inv = __fdividef(1.0f, total);

    float4 o4 = make_float4(e[0] * inv, e[1] * inv, e[2] * inv, e[3] * inv);
    *(float4*)(out + (size_t)bt * SRC + tid * 4) = o4;
}

// ---------------------------------------------------------------------------
extern "C" void kernel_launch(void* const* d_in, const int* in_sizes, int n_in,
                              void* d_out, int out_size) {
    const float* query = (const float*)d_in[0];  // [4,256,256]
    const float* key   = (const float*)d_in[1];  // [4,1024,256]
    const float* Wq    = (const float*)d_in[2];  // [256,256]
    const float* Wk    = (const float*)d_in[3];  // [256,256]
    const float* v     = (const float*)d_in[4];  // [256]
    const float* vb    = (const float*)d_in[5];  // [1]
    float* out = (float*)d_out;                  // [4,256,1024]

    gemm_both_kernel<<<320, 256>>>(query, key, Wq, Wk);
    attn_kernel<<<BSZ * TGT, 256>>>(v, vb, out);
}

// round 10
// speedup vs baseline: 3.8488x; 1.0023x over previous
#include <cuda_runtime.h>
#include <cuda_fp16.h>

// Problem shape (fixed by the reference):
//   query [4,256,256], key [4,1024,256], Wq [256,256], Wk [256,256], v [256], v_bias [1]
//   out = softmax_s( sum_h v[h]*tanh(q[bt,h]+k[bs,h]) + vb )  -> [4,256,1024] fp32
#define BSZ 4
#define TGT 256
#define SRC 1024
#define HS  256

__device__ __align__(16) float  g_q[BSZ * TGT * HS];     // [1024, 256] fp32
__device__ __align__(16) __half g_kT16[BSZ * HS * SRC];  // [4, 256 h, 1024 s] fp16, TRANSPOSED

// ---------------------------------------------------------------------------
// Fused NT GEMM, one launch (320 blocks).
// Blocks [0,64):   g_q    = query @ Wq^T                (fp32 row-major)
// Blocks [64,320): g_kT16 = half((key @ Wk^T)^T)        (fp16, h-major)
// BM=BN=64, BK=16, 256 threads, 4x4 per thread. N=K=256.
// ---------------------------------------------------------------------------
__global__ void __launch_bounds__(256) gemm_both_kernel(const float* __restrict__ query,
                                                        const float* __restrict__ key,
                                                        const float* __restrict__ Wq,
                                                        const float* __restrict__ Wk) {
    const int K = HS, N = HS;

    const float* __restrict__ A;
    const float* __restrict__ B;
    int local;
    const bool is_q = blockIdx.x < 64;
    if (is_q) { A = query; B = Wq; local = blockIdx.x; }
    else      { A = key;   B = Wk; local = blockIdx.x - 64; }
    const int bm0 = (local >> 2) * 64;
    const int bn0 = (local & 3) * 64;

    __shared__ float sA[16][64];
    __shared__ float sB[16][64];

    const int tid = threadIdx.x;
    const int lrow = tid >> 2;
    const int lc4  = (tid & 3) << 2;
    const int ty = tid >> 4;
    const int tx = tid & 15;

    float acc[4][4];
#pragma unroll
    for (int i = 0; i < 4; i++)
#pragma unroll
        for (int j = 0; j < 4; j++) acc[i][j] = 0.f;

    for (int k0 = 0; k0 < K; k0 += 16) {
        float4 a = *(const float4*)&A[(bm0 + lrow) * K + k0 + lc4];
        float4 b = *(const float4*)&B[(bn0 + lrow) * K + k0 + lc4];
        __syncthreads();
        sA[lc4 + 0][lrow] = a.x; sA[lc4 + 1][lrow] = a.y;
        sA[lc4 + 2][lrow] = a.z; sA[lc4 + 3][lrow] = a.w;
        sB[lc4 + 0][lrow] = b.x; sB[lc4 + 1][lrow] = b.y;
        sB[lc4 + 2][lrow] = b.z; sB[lc4 + 3][lrow] = b.w;
        __syncthreads();
#pragma unroll
        for (int kk = 0; kk < 16; kk++) {
            float4 ar = ((const float4*)&sA[kk][0])[ty];
            float4 br = ((const float4*)&sB[kk][0])[tx];
            float am[4] = {ar.x, ar.y, ar.z, ar.w};
            float bn[4] = {br.x, br.y, br.z, br.w};
#pragma unroll
            for (int i = 0; i < 4; i++)
#pragma unroll
                for (int j = 0; j < 4; j++) acc[i][j] = fmaf(am[i], bn[j], acc[i][j]);
        }
    }

    if (is_q) {
#pragma unroll
        for (int i = 0; i < 4; i++) {
            float4 o = make_float4(acc[i][0], acc[i][1], acc[i][2], acc[i][3]);
            *(float4*)&g_q[(bm0 + ty * 4 + i) * N + bn0 + tx * 4] = o;
        }
    } else {
        // transposed fp16 store: C[m][n] -> g_kT16[b][h=n][s=m%1024]
#pragma unroll
        for (int i = 0; i < 4; i++) {
            const int m = bm0 + ty * 4 + i;
            const int bb = m >> 10;
            const int s  = m & (SRC - 1);
#pragma unroll
            for (int j = 0; j < 4; j++) {
                const int h = bn0 + tx * 4 + j;
                g_kT16[((size_t)bb * HS + h) * SRC + s] = __float2half_rn(acc[i][j]);
            }
        }
    }
}

// ---------------------------------------------------------------------------
__device__ __forceinline__ __half2 tanh_h2(__half2 x) {
    __half2 y;
    asm("tanh.approx.f16x2 %0, %1;"
        : "=r"(*(unsigned int*)&y) : "r"(*(const unsigned int*)&x));
    return y;
}

// ---------------------------------------------------------------------------
// Fused energy + softmax. Block per (b,t), 256 threads; thread owns the 4
// CONSECUTIVE s in [4*tid, 4*tid+4).
// Prologue builds broadcast half2 tables sq2/sv2 (one LDS.128 covers 4 h),
// so the inner loop is pure LDG/LDS + HADD2 + MUFU.TANH.f16x2 + HFMA2 with
// split accumulators; fp32 re-accumulation every 16 h bounds rounding.
// ---------------------------------------------------------------------------
__global__ void __launch_bounds__(256) attn_kernel(const float* __restrict__ v,
                                                   const float* __restrict__ vbias,
                                                   float* __restrict__ out) {
    const int bt = blockIdx.x;          // 0..1023
    const int b  = bt >> 8;
    const int tid = threadIdx.x;

    __shared__ __align__(16) __half2 sq2[HS];   // (q_h, q_h) broadcast pairs
    __shared__ __align__(16) __half2 sv2[HS];   // (v_h, v_h)
    __shared__ float red[8];

    {
        const float qh = g_q[bt * HS + tid];
        const float vh = v[tid];
        sq2[tid] = __float2half2_rn(qh);
        sv2[tid] = __float2half2_rn(vh);
    }
    __syncthreads();

    // Thread's 4 consecutive s live at uint2 index tid of every h-row.
    const uint2* __restrict__ kp =
        ((const uint2*)(g_kT16 + (size_t)b * HS * SRC)) + tid;

    float f0 = 0.f, f1 = 0.f, f2 = 0.f, f3 = 0.f;   // fp32 master accumulators

    for (int c = 0; c < 16; c++) {                   // 16 chunks x 16 h
        const __half2 z = __float2half2_rn(0.f);
        __half2 a01[2] = { z, z };
        __half2 a23[2] = { z, z };
#pragma unroll
        for (int u4 = 0; u4 < 4; u4++) {             // 4 h4-steps per chunk
            const int h4 = c * 4 + u4;
            uint4 qb = ((const uint4*)sq2)[h4];      // 4 broadcast q-pairs
            uint4 vbq = ((const uint4*)sv2)[h4];     // 4 broadcast v-pairs
            uint2 kk[4];
#pragma unroll
            for (int u = 0; u < 4; u++)
                kk[u] = kp[(h4 * 4 + u) * (SRC / 4)];
            const unsigned qs[4] = { qb.x, qb.y, qb.z, qb.w };
            const unsigned vs[4] = { vbq.x, vbq.y, vbq.z, vbq.w };
#pragma unroll
            for (int u = 0; u < 4; u++) {
                __half2 q2  = *(const __half2*)&qs[u];
                __half2 v2  = *(const __half2*)&vs[u];
                __half2 k01 = *(const __half2*)&kk[u].x;
                __half2 k23 = *(const __half2*)&kk[u].y;
                __half2 t01 = tanh_h2(__hadd2(q2, k01));
                __half2 t23 = tanh_h2(__hadd2(q2, k23));
                a01[u & 1] = __hfma2(v2, t01, a01[u & 1]);
                a23[u & 1] = __hfma2(v2, t23, a23[u & 1]);
            }
        }
        float2 pa = __half22float2(a01[0]);
        float2 pb = __half22float2(a01[1]);
        float2 pc = __half22float2(a23[0]);
        float2 pd = __half22float2(a23[1]);
        f0 += pa.x + pb.x; f1 += pa.y + pb.y;
        f2 += pc.x + pd.x; f3 += pc.y + pd.y;
    }

    const float vb = vbias[0];
    float sc[4] = { f0 + vb, f1 + vb, f2 + vb, f3 + vb };

    // ---- block softmax over the 1024 scores (4 consecutive per thread) ----
    const int lane = tid & 31, wid = tid >> 5;

    float m = fmaxf(fmaxf(sc[0], sc[1]), fmaxf(sc[2], sc[3]));
#pragma unroll
    for (int o = 16; o > 0; o >>= 1) m = fmaxf(m, __shfl_xor_sync(0xffffffffu, m, o));
    if (lane == 0) red[wid] = m;
    __syncthreads();
    m = red[0];
#pragma unroll
    for (int i = 1; i < 8; i++) m = fmaxf(m, red[i]);
    __syncthreads();   // red reused below

    float e[4];
    float ssum = 0.f;
#pragma unroll
    for (int j = 0; j < 4; j++) { e[j] = __expf(sc[j] - m); ssum += e[j]; }
#pragma unroll
    for (int o = 16; o > 0; o >>= 1) ssum += __shfl_xor_sync(0xffffffffu, ssum, o);
    if (lane == 0) red[wid] = ssum;
    __syncthreads();
    float total = red[0];
#pragma unroll
    for (int i = 1; i < 8; i++) total += red[i];
    const float inv = __fdividef(1.0f, total);

    float4 o4 = make_float4(e[0] * inv, e[1] * inv, e[2] * inv, e[3] * inv);
    *(float4*)(out + (size_t)bt * SRC + tid * 4) = o4;
}

// ---------------------------------------------------------------------------
extern "C" void kernel_launch(void* const* d_in, const int* in_sizes, int n_in,
                              void* d_out, int out_size) {
    const float* query = (const float*)d_in[0];  // [4,256,256]
    const float* key   = (const float*)d_in[1];  // [4,1024,256]
    const float* Wq    = (const float*)d_in[2];  // [256,256]
    const float* Wk    = (const float*)d_in[3];  // [256,256]
    const float* v     = (const float*)d_in[4];  // [256]
    const float* vb    = (const float*)d_in[5];  // [1]
    float* out = (float*)d_out;                  // [4,256,1024]

    gemm_both_kernel<<<320, 256>>>(query, key, Wq, Wk);
    attn_kernel<<<BSZ * TGT, 256>>>(v, vb, out);
}

// round 11
// speedup vs baseline: 3.8726x; 1.0062x over previous
#include <cuda_runtime.h>
#include <cuda_fp16.h>

// Problem shape (fixed by the reference):
//   query [4,256,256], key [4,1024,256], Wq [256,256], Wk [256,256], v [256], v_bias [1]
//   out = softmax_s( sum_h v[h]*tanh(q[bt,h]+k[bs,h]) + vb )  -> [4,256,1024] fp32
#define BSZ 4
#define TGT 256
#define SRC 1024
#define HS  256

__device__ __align__(16) float  g_q[BSZ * TGT * HS];     // [1024, 256] fp32
__device__ __align__(16) __half g_kT16[BSZ * HS * SRC];  // [4, 256 h, 1024 s] fp16, TRANSPOSED

// ---------------------------------------------------------------------------
// Packed f32x2 helpers (exact fp32 semantics).
// ---------------------------------------------------------------------------
typedef unsigned long long u64t;

__device__ __forceinline__ u64t f2pack(float lo, float hi) {
    u64t r; asm("mov.b64 %0, {%1, %2};" : "=l"(r) : "f"(lo), "f"(hi)); return r;
}
__device__ __forceinline__ void f2unpack(u64t p, float& lo, float& hi) {
    asm("mov.b64 {%0, %1}, %2;" : "=f"(lo), "=f"(hi) : "l"(p));
}
__device__ __forceinline__ u64t f2fma(u64t a, u64t b, u64t c) {
    u64t r; asm("fma.rn.f32x2 %0, %1, %2, %3;" : "=l"(r) : "l"(a), "l"(b), "l"(c)); return r;
}

// ---------------------------------------------------------------------------
// Fused NT GEMM, one launch (320 blocks). Software-pipelined (register
// prefetch of the next K-tile hides L2 latency under compute) and packed
// f32x2 FFMA (row pairs) -> half the fma-pipe instructions, same fp32 math.
// Blocks [0,64):   g_q    = query @ Wq^T                (fp32 row-major)
// Blocks [64,320): g_kT16 = half((key @ Wk^T)^T)        (fp16, h-major)
// BM=BN=64, BK=16, 256 threads, 4x4 per thread. N=K=256.
// ---------------------------------------------------------------------------
__global__ void __launch_bounds__(256) gemm_both_kernel(const float* __restrict__ query,
                                                        const float* __restrict__ key,
                                                        const float* __restrict__ Wq,
                                                        const float* __restrict__ Wk) {
    const int K = HS, N = HS;

    const float* __restrict__ A;
    const float* __restrict__ B;
    int local;
    const bool is_q = blockIdx.x < 64;
    if (is_q) { A = query; B = Wq; local = blockIdx.x; }
    else      { A = key;   B = Wk; local = blockIdx.x - 64; }
    const int bm0 = (local >> 2) * 64;
    const int bn0 = (local & 3) * 64;

    __shared__ float sA[16][64];
    __shared__ float sB[16][64];

    const int tid = threadIdx.x;
    const int lrow = tid >> 2;          // 0..63
    const int lc4  = (tid & 3) << 2;    // 0,4,8,12
    const int ty = tid >> 4;            // 0..15 -> m sub-tile
    const int tx = tid & 15;            // 0..15 -> n sub-tile

    const float* Arow = &A[(bm0 + lrow) * K + lc4];
    const float* Brow = &B[(bn0 + lrow) * K + lc4];

    // acc2[p][j]: packed rows (ty*4+2p, ty*4+2p+1), col bn0+tx*4+j
    u64t acc2[2][4];
#pragma unroll
    for (int p = 0; p < 2; p++)
#pragma unroll
        for (int j = 0; j < 4; j++) acc2[p][j] = f2pack(0.f, 0.f);

    // Prefetch first tile
    float4 pa = *(const float4*)(Arow + 0);
    float4 pb = *(const float4*)(Brow + 0);

    for (int k0 = 0; k0 < K; k0 += 16) {
        sA[lc4 + 0][lrow] = pa.x; sA[lc4 + 1][lrow] = pa.y;
        sA[lc4 + 2][lrow] = pa.z; sA[lc4 + 3][lrow] = pa.w;
        sB[lc4 + 0][lrow] = pb.x; sB[lc4 + 1][lrow] = pb.y;
        sB[lc4 + 2][lrow] = pb.z; sB[lc4 + 3][lrow] = pb.w;
        __syncthreads();

        if (k0 + 16 < K) {                 // issue next-tile loads early
            pa = *(const float4*)(Arow + k0 + 16);
            pb = *(const float4*)(Brow + k0 + 16);
        }

#pragma unroll
        for (int kk = 0; kk < 16; kk++) {
            float4 ar = ((const float4*)&sA[kk][0])[ty];
            float4 br = ((const float4*)&sB[kk][0])[tx];
            u64t am01 = f2pack(ar.x, ar.y);
            u64t am23 = f2pack(ar.z, ar.w);
            u64t b0 = f2pack(br.x, br.x);
            u64t b1 = f2pack(br.y, br.y);
            u64t b2 = f2pack(br.z, br.z);
            u64t b3 = f2pack(br.w, br.w);
            acc2[0][0] = f2fma(am01, b0, acc2[0][0]);
            acc2[0][1] = f2fma(am01, b1, acc2[0][1]);
            acc2[0][2] = f2fma(am01, b2, acc2[0][2]);
            acc2[0][3] = f2fma(am01, b3, acc2[0][3]);
            acc2[1][0] = f2fma(am23, b0, acc2[1][0]);
            acc2[1][1] = f2fma(am23, b1, acc2[1][1]);
            acc2[1][2] = f2fma(am23, b2, acc2[1][2]);
            acc2[1][3] = f2fma(am23, b3, acc2[1][3]);
        }
        __syncthreads();
    }

    // Unpack to per-row float4s
    float accr[4][4];
#pragma unroll
    for (int p = 0; p < 2; p++)
#pragma unroll
        for (int j = 0; j < 4; j++)
            f2unpack(acc2[p][j], accr[2 * p][j], accr[2 * p + 1][j]);

    if (is_q) {
#pragma unroll
        for (int i = 0; i < 4; i++) {
            float4 o = make_float4(accr[i][0], accr[i][1], accr[i][2], accr[i][3]);
            *(float4*)&g_q[(bm0 + ty * 4 + i) * N + bn0 + tx * 4] = o;
        }
    } else {
        // transposed fp16 store: C[m][n] -> g_kT16[b][h=n][s=m%1024]
#pragma unroll
        for (int i = 0; i < 4; i++) {
            const int m = bm0 + ty * 4 + i;
            const int bb = m >> 10;
            const int s  = m & (SRC - 1);
#pragma unroll
            for (int j = 0; j < 4; j++) {
                const int h = bn0 + tx * 4 + j;
                g_kT16[((size_t)bb * HS + h) * SRC + s] = __float2half_rn(accr[i][j]);
            }
        }
    }
}

// ---------------------------------------------------------------------------
__device__ __forceinline__ __half2 tanh_h2(__half2 x) {
    __half2 y;
    asm("tanh.approx.f16x2 %0, %1;"
        : "=r"(*(unsigned int*)&y) : "r"(*(const unsigned int*)&x));
    return y;
}

// ---------------------------------------------------------------------------
// Fused energy + softmax (UNCHANGED from the 70.2 µs R10 kernel).
// Block per (b,t), 256 threads; thread owns s in [4*tid, 4*tid+4).
// ---------------------------------------------------------------------------
__global__ void __launch_bounds__(256) attn_kernel(const float* __restrict__ v,
                                                   const float* __restrict__ vbias,
                                                   float* __restrict__ out) {
    const int bt = blockIdx.x;          // 0..1023
    const int b  = bt >> 8;
    const int tid = threadIdx.x;

    __shared__ __align__(16) __half2 sq2[HS];   // (q_h, q_h) broadcast pairs
    __shared__ __align__(16) __half2 sv2[HS];   // (v_h, v_h)
    __shared__ float red[8];

    {
        const float qh = g_q[bt * HS + tid];
        const float vh = v[tid];
        sq2[tid] = __float2half2_rn(qh);
        sv2[tid] = __float2half2_rn(vh);
    }
    __syncthreads();

    const uint2* __restrict__ kp =
        ((const uint2*)(g_kT16 + (size_t)b * HS * SRC)) + tid;

    float f0 = 0.f, f1 = 0.f, f2 = 0.f, f3 = 0.f;   // fp32 master accumulators

    for (int c = 0; c < 16; c++) {                   // 16 chunks x 16 h
        const __half2 z = __float2half2_rn(0.f);
        __half2 a01[2] = { z, z };
        __half2 a23[2] = { z, z };
#pragma unroll
        for (int u4 = 0; u4 < 4; u4++) {             // 4 h4-steps per chunk
            const int h4 = c * 4 + u4;
            uint4 qb = ((const uint4*)sq2)[h4];      // 4 broadcast q-pairs
            uint4 vbq = ((const uint4*)sv2)[h4];     // 4 broadcast v-pairs
            uint2 kk[4];
#pragma unroll
            for (int u = 0; u < 4; u++)
                kk[u] = kp[(h4 * 4 + u) * (SRC / 4)];
            const unsigned qs[4] = { qb.x, qb.y, qb.z, qb.w };
            const unsigned vs[4] = { vbq.x, vbq.y, vbq.z, vbq.w };
#pragma unroll
            for (int u = 0; u < 4; u++) {
                __half2 q2  = *(const __half2*)&qs[u];
                __half2 v2  = *(const __half2*)&vs[u];
                __half2 k01 = *(const __half2*)&kk[u].x;
                __half2 k23 = *(const __half2*)&kk[u].y;
                __half2 t01 = tanh_h2(__hadd2(q2, k01));
                __half2 t23 = tanh_h2(__hadd2(q2, k23));
                a01[u & 1] = __hfma2(v2, t01, a01[u & 1]);
                a23[u & 1] = __hfma2(v2, t23, a23[u & 1]);
            }
        }
        float2 pa = __half22float2(a01[0]);
        float2 pb = __half22float2(a01[1]);
        float2 pc = __half22float2(a23[0]);
        float2 pd = __half22float2(a23[1]);
        f0 += pa.x + pb.x; f1 += pa.y + pb.y;
        f2 += pc.x + pd.x; f3 += pc.y + pd.y;
    }

    const float vb = vbias[0];
    float sc[4] = { f0 + vb, f1 + vb, f2 + vb, f3 + vb };

    // ---- block softmax over the 1024 scores (4 consecutive per thread) ----
    const int lane = tid & 31, wid = tid >> 5;

    float m = fmaxf(fmaxf(sc[0], sc[1]), fmaxf(sc[2], sc[3]));
#pragma unroll
    for (int o = 16; o > 0; o >>= 1) m = fmaxf(m, __shfl_xor_sync(0xffffffffu, m, o));
    if (lane == 0) red[wid] = m;
    __syncthreads();
    m = red[0];
#pragma unroll
    for (int i = 1; i < 8; i++) m = fmaxf(m, red[i]);
    __syncthreads();   // red reused below

    float e[4];
    float ssum = 0.f;
#pragma unroll
    for (int j = 0; j < 4; j++) { e[j] = __expf(sc[j] - m); ssum += e[j]; }
#pragma unroll
    for (int o = 16; o > 0; o >>= 1) ssum += __shfl_xor_sync(0xffffffffu, ssum, o);
    if (lane == 0) red[wid] = ssum;
    __syncthreads();
    float total = red[0];
#pragma unroll
    for (int i = 1; i < 8; i++) total += red[i];
    const float inv = __fdividef(1.0f, total);

    float4 o4 = make_float4(e[0] * inv, e[1] * inv, e[2] * inv, e[3] * inv);
    *(float4*)(out + (size_t)bt * SRC + tid * 4) = o4;
}

// ---------------------------------------------------------------------------
extern "C" void kernel_launch(void* const* d_in, const int* in_sizes, int n_in,
                              void* d_out, int out_size) {
    const float* query = (const float*)d_in[0];  // [4,256,256]
    const float* key   = (const float*)d_in[1];  // [4,1024,256]
    const float* Wq    = (const float*)d_in[2];  // [256,256]
    const float* Wk    = (const float*)d_in[3];  // [256,256]
    const float* v     = (const float*)d_in[4];  // [256]
    const float* vb    = (const float*)d_in[5];  // [1]
    float* out = (float*)d_out;                  // [4,256,1024]

    gemm_both_kernel<<<320, 256>>>(query, key, Wq, Wk);
    attn_kernel<<<BSZ * TGT, 256>>>(v, vb, out);
}